// round 7
// baseline (speedup 1.0000x reference)
#include <cuda_runtime.h>
#include <cuda_bf16.h>
#include <stdint.h>

// GCN mean aggregation:
//   out[i, :] = mean over {nodes[i]} ∪ neigh_idx[i,0..31] of features[idx, :]
// features [V=100000, D=128] f32, nodes [B] int{32|64}, neigh [B,32] int{32|64}.
//
// Warp per node, single-line LDG.32 gather (32 lanes x 4B = one 128B line per
// instruction; 4 per 512B row). CHANGE vs best (47.6us): feature loads use
// ld.global.cg -> L2-only, NO L1 allocation. L1 hit prob on the random gather
// is ~0.5% (456 resident rows / 100000), so L1 fills are pure overhead on the
// L1tex conduit (tag work, MSHR, fill bandwidth). evict_last L2 policy keeps
// the 51MB table resident; index loads / stores are streaming (.cs).

static constexpr int KN = 32;
static constexpr float INV_CNT = 1.0f / 33.0f;

__device__ __forceinline__ uint64_t make_keep_policy() {
    uint64_t pol;
    asm("createpolicy.fractional.L2::evict_last.b64 %0, 1.0;" : "=l"(pol));
    return pol;
}

// L2-only (no L1 allocate) + evict_last policy.
__device__ __forceinline__ float ldg_cg_keep(const float* p, uint64_t pol) {
    float v;
    asm volatile("ld.global.cg.L2::cache_hint.f32 %0, [%1], %2;"
                 : "=f"(v) : "l"(p), "l"(pol));
    return v;
}

__device__ __forceinline__ void stg_stream1(float* p, float v) {
    asm volatile("st.global.cs.f32 [%0], %1;" :: "l"(p), "f"(v) : "memory");
}

__device__ __forceinline__ int2 ldg_cs32x2(const int* p) {
    int2 v;
    asm volatile("ld.global.cs.v2.s32 {%0,%1}, [%2];"
                 : "=r"(v.x), "=r"(v.y) : "l"(p));
    return v;
}

__device__ __forceinline__ long long ldg_cs64(const long long* p) {
    long long v;
    asm volatile("ld.global.cs.s64 %0, [%1];" : "=l"(v) : "l"(p));
    return v;
}

__device__ __forceinline__ int ldg_cs32(const int* p) {
    int v;
    asm volatile("ld.global.cs.s32 %0, [%1];" : "=r"(v) : "l"(p));
    return v;
}

__global__ __launch_bounds__(256) void gcn_agg_kernel(
    const float* __restrict__ feat,
    const void*  __restrict__ nodes,
    const void*  __restrict__ neigh,
    float*       __restrict__ out,
    int B)
{
    const int node = (blockIdx.x * blockDim.x + threadIdx.x) >> 5;
    const int lane = threadIdx.x & 31;
    if (node >= B) return;

    // Inline index-dtype detection (JAX may demote int64 -> int32):
    // little-endian int64 values < 2^31 have every odd 32-bit word zero.
    const int2 probe = ldg_cs32x2((const int*)neigh + 2 * lane);
    const bool is64 = (__ballot_sync(0xffffffffu, probe.y == 0) == 0xffffffffu);

    // Fetch this node's indices: lane j holds neighbor j (coalesced).
    int my_idx, self_idx;
    if (is64) {
        my_idx   = (int)ldg_cs64((const long long*)neigh + (long long)node * KN + lane);
        self_idx = (int)ldg_cs64((const long long*)nodes + node);
    } else {
        my_idx   = ldg_cs32((const int*)neigh + (long long)node * KN + lane);
        self_idx = ldg_cs32((const int*)nodes + node);
    }

    const uint64_t pol = make_keep_policy();

    float acc0, acc1, acc2, acc3;
    {
        const float* r = feat + (long long)self_idx * 128 + lane;
        acc0 = ldg_cg_keep(r,      pol);
        acc1 = ldg_cg_keep(r + 32, pol);
        acc2 = ldg_cg_keep(r + 64, pol);
        acc3 = ldg_cg_keep(r + 96, pol);
    }
#pragma unroll
    for (int j = 0; j < KN; j++) {
        const int idx = __shfl_sync(0xffffffffu, my_idx, j);
        const float* r = feat + (long long)idx * 128 + lane;
        acc0 += ldg_cg_keep(r,      pol);
        acc1 += ldg_cg_keep(r + 32, pol);
        acc2 += ldg_cg_keep(r + 64, pol);
        acc3 += ldg_cg_keep(r + 96, pol);
    }

    float* op = out + (long long)node * 128 + lane;
    stg_stream1(op,      acc0 * INV_CNT);
    stg_stream1(op + 32, acc1 * INV_CNT);
    stg_stream1(op + 64, acc2 * INV_CNT);
    stg_stream1(op + 96, acc3 * INV_CNT);
}

extern "C" void kernel_launch(void* const* d_in, const int* in_sizes, int n_in,
                              void* d_out, int out_size) {
    const float* feat  = (const float*)d_in[0];
    const void*  nodes = d_in[1];
    const void*  neigh = d_in[2];
    float*       out   = (float*)d_out;

    const int B = in_sizes[1];  // 50000

    const int threads = 256;   // 8 warps = 8 nodes per block
    const int blocks  = (B * 32 + threads - 1) / threads;
    gcn_agg_kernel<<<blocks, threads>>>(feat, nodes, neigh, out, B);
}

// round 8
// speedup vs baseline: 1.0040x; 1.0040x over previous
#include <cuda_runtime.h>
#include <cuda_bf16.h>
#include <stdint.h>

// GCN mean aggregation:
//   out[i, :] = mean over {nodes[i]} ∪ neigh_idx[i,0..31] of features[idx, :]
// features [V=100000, D=128] f32, nodes [B] int{32|64}, neigh [B,32] int{32|64}.
//
// Warp per node, single-line LDG.32 gather (32 lanes x 4B = one 128B line per
// instruction, 4 per 512B row). Measured wall: ~75% of L2-hit slice bandwidth
// (random-hash temporal imbalance). This round: raise chip-wide in-flight
// requests -- 2-row load groups (8 independent scalar loads, 8 accumulators)
// at a 40-reg budget so batching doubles while occupancy stays ~48 warps/SM.
//  - feature loads: .nc + L2::evict_last policy (51MB table stays resident)
//  - index loads / output stores: streaming (.cs)
//  - index dtype (int64 vs JAX-demoted int32) probed inline per warp.

static constexpr int KN = 32;
static constexpr float INV_CNT = 1.0f / 33.0f;

__device__ __forceinline__ uint64_t make_keep_policy() {
    uint64_t pol;
    asm("createpolicy.fractional.L2::evict_last.b64 %0, 1.0;" : "=l"(pol));
    return pol;
}

__device__ __forceinline__ float ldg_keep1(const float* p, uint64_t pol) {
    float v;
    asm volatile("ld.global.nc.L2::cache_hint.f32 %0, [%1], %2;"
                 : "=f"(v) : "l"(p), "l"(pol));
    return v;
}

__device__ __forceinline__ void stg_stream1(float* p, float v) {
    asm volatile("st.global.cs.f32 [%0], %1;" :: "l"(p), "f"(v) : "memory");
}

__device__ __forceinline__ int2 ldg_cs32x2(const int* p) {
    int2 v;
    asm volatile("ld.global.cs.v2.s32 {%0,%1}, [%2];"
                 : "=r"(v.x), "=r"(v.y) : "l"(p));
    return v;
}

__device__ __forceinline__ long long ldg_cs64(const long long* p) {
    long long v;
    asm volatile("ld.global.cs.s64 %0, [%1];" : "=l"(v) : "l"(p));
    return v;
}

__device__ __forceinline__ int ldg_cs32(const int* p) {
    int v;
    asm volatile("ld.global.cs.s32 %0, [%1];" : "=r"(v) : "l"(p));
    return v;
}

__global__ __launch_bounds__(256, 6) void gcn_agg_kernel(
    const float* __restrict__ feat,
    const void*  __restrict__ nodes,
    const void*  __restrict__ neigh,
    float*       __restrict__ out,
    int B)
{
    const int node = (blockIdx.x * blockDim.x + threadIdx.x) >> 5;
    const int lane = threadIdx.x & 31;
    if (node >= B) return;

    // Inline index-dtype detection: little-endian int64 values < 2^31 have
    // every odd 32-bit word zero (probe first 64 words of neigh).
    const int2 probe = ldg_cs32x2((const int*)neigh + 2 * lane);
    const bool is64 = (__ballot_sync(0xffffffffu, probe.y == 0) == 0xffffffffu);

    // Fetch this node's indices: lane j holds neighbor j (coalesced).
    int my_idx, self_idx;
    if (is64) {
        my_idx   = (int)ldg_cs64((const long long*)neigh + (long long)node * KN + lane);
        self_idx = (int)ldg_cs64((const long long*)nodes + node);
    } else {
        my_idx   = ldg_cs32((const int*)neigh + (long long)node * KN + lane);
        self_idx = ldg_cs32((const int*)nodes + node);
    }

    const uint64_t pol = make_keep_policy();

    // 8 independent accumulators; each loop iteration issues 8 independent
    // single-line loads (2 rows x 4 slices) before any consuming FADD.
    float a0, a1, a2, a3, b0, b1, b2, b3;
    {
        const float* r = feat + (long long)self_idx * 128 + lane;
        a0 = ldg_keep1(r,      pol);
        a1 = ldg_keep1(r + 32, pol);
        a2 = ldg_keep1(r + 64, pol);
        a3 = ldg_keep1(r + 96, pol);
    }
    b0 = b1 = b2 = b3 = 0.f;

#pragma unroll
    for (int j = 0; j < KN; j += 2) {
        const int ia = __shfl_sync(0xffffffffu, my_idx, j);
        const int ib = __shfl_sync(0xffffffffu, my_idx, j + 1);
        const float* ra = feat + (long long)ia * 128 + lane;
        const float* rb = feat + (long long)ib * 128 + lane;
        const float va0 = ldg_keep1(ra,      pol);
        const float va1 = ldg_keep1(ra + 32, pol);
        const float va2 = ldg_keep1(ra + 64, pol);
        const float va3 = ldg_keep1(ra + 96, pol);
        const float vb0 = ldg_keep1(rb,      pol);
        const float vb1 = ldg_keep1(rb + 32, pol);
        const float vb2 = ldg_keep1(rb + 64, pol);
        const float vb3 = ldg_keep1(rb + 96, pol);
        a0 += va0; a1 += va1; a2 += va2; a3 += va3;
        b0 += vb0; b1 += vb1; b2 += vb2; b3 += vb3;
    }

    float* op = out + (long long)node * 128 + lane;
    stg_stream1(op,      (a0 + b0) * INV_CNT);
    stg_stream1(op + 32, (a1 + b1) * INV_CNT);
    stg_stream1(op + 64, (a2 + b2) * INV_CNT);
    stg_stream1(op + 96, (a3 + b3) * INV_CNT);
}

extern "C" void kernel_launch(void* const* d_in, const int* in_sizes, int n_in,
                              void* d_out, int out_size) {
    const float* feat  = (const float*)d_in[0];
    const void*  nodes = d_in[1];
    const void*  neigh = d_in[2];
    float*       out   = (float*)d_out;

    const int B = in_sizes[1];  // 50000

    const int threads = 256;   // 8 warps = 8 nodes per block
    const int blocks  = (B * 32 + threads - 1) / threads;
    gcn_agg_kernel<<<blocks, threads>>>(feat, nodes, neigh, out, B);
}